// round 14
// baseline (speedup 1.0000x reference)
#include <cuda_runtime.h>
#include <cuda_bf16.h>
#include <math.h>
#include <stdint.h>

#define B_TOT   4096
#define NWIN    64
#define NTOK    49
#define DIM     192
#define NHEAD   6
#define HDIM    32
#define M_ROWS  (B_TOT * NTOK)     /* 200704 */
#define QKV_N   576
#define NN      (NTOK * NTOK)      /* 2401 */

// Scratch (no cudaMalloc allowed); referenced directly from kernels.
__device__ float    g_qkv[(size_t)M_ROWS * QKV_N];        // 462 MB fp32
__device__ uint32_t g_xhl[(size_t)M_ROWS * DIM];          // 154 MB {hi,lo} words
__device__ uint32_t g_ctxhl[(size_t)M_ROWS * DIM];        // 154 MB {hi,lo} words
__device__ uint32_t g_wqkv[(size_t)QKV_N * DIM];          // 442 KB
__device__ uint32_t g_wproj[(size_t)DIM * DIM];           // 147 KB
__device__ float    g_bm[(size_t)NWIN * NHEAD * NN];      // 3.7 MB bias+mask

__device__ __forceinline__ uint32_t pack_bf16x2(float x, float y) {
    __nv_bfloat162 t = __floats2bfloat162_rn(x, y);   // x -> low 16 bits
    return *reinterpret_cast<uint32_t*>(&t);
}

// ---------------------------------------------------------------------------
// fp32 -> interleaved {hi,lo} bf16x2 pair conversion (element pair per thread)
// ---------------------------------------------------------------------------
__device__ __forceinline__ uint2 split_pair(float2 f) {
    const float h0 = __bfloat162float(__float2bfloat16_rn(f.x));
    const float h1 = __bfloat162float(__float2bfloat16_rn(f.y));
    return make_uint2(pack_bf16x2(h0, h1), pack_bf16x2(f.x - h0, f.y - h1));
}

__global__ __launch_bounds__(256)
void cvt_x_kernel(const float* __restrict__ src)
{
    const int i = blockIdx.x * 256 + threadIdx.x;     // pair index
    const int npairs = M_ROWS * DIM / 2;
    if (i < npairs)
        reinterpret_cast<uint2*>(g_xhl)[i] =
            split_pair(reinterpret_cast<const float2*>(src)[i]);
}

__global__ __launch_bounds__(256)
void cvt_w_kernel(const float* __restrict__ wqkv, const float* __restrict__ wproj)
{
    const int i = blockIdx.x * 256 + threadIdx.x;
    const int nq = QKV_N * DIM / 2;                   // 55296
    const int np = DIM * DIM / 2;                     // 18432
    if (i < nq)
        reinterpret_cast<uint2*>(g_wqkv)[i] =
            split_pair(reinterpret_cast<const float2*>(wqkv)[i]);
    if (i < np)
        reinterpret_cast<uint2*>(g_wproj)[i] =
            split_pair(reinterpret_cast<const float2*>(wproj)[i]);
}

// ---------------------------------------------------------------------------
// Precompute bm[(mb*NHEAD+h)][e] = rpb[rel_idx[e]*NHEAD+h] + mask[mb][e]
// ---------------------------------------------------------------------------
__global__ __launch_bounds__(256)
void bm_kernel(const float* __restrict__ mask,
               const float* __restrict__ rpb_table,
               const int*   __restrict__ rel_idx)
{
    const int mb = blockIdx.x / NHEAD;
    const int h  = blockIdx.x % NHEAD;
    float* dst = &g_bm[(size_t)blockIdx.x * NN];
    const float* msk = &mask[(size_t)mb * NN];
    for (int e = threadIdx.x; e < NN; e += 256)
        dst[e] = rpb_table[rel_idx[e] * NHEAD + h] + msk[e];
}

// ---------------------------------------------------------------------------
// bf16x3 tensor-core GEMM on pre-split interleaved {hi,lo} inputs.
// C[M,N] = A[M,K] @ W^T + bias. A_hl, W_hl: word-per-element interleaved.
// BM=128, BN=64, BK=16, 256 threads (8 warps, 4x2 grid of 32x32 warp tiles).
// Hot loop: 3 LDG.128 + 3 STS.128 + 16 LDS.64 + 24 MMA per warp-iter.
// ---------------------------------------------------------------------------
__device__ __forceinline__ void mma_bf16(float* d, const uint32_t* a, const uint32_t* b) {
    asm volatile(
        "mma.sync.aligned.m16n8k16.row.col.f32.bf16.bf16.f32 "
        "{%0,%1,%2,%3}, {%4,%5,%6,%7}, {%8,%9}, {%0,%1,%2,%3};"
        : "+f"(d[0]), "+f"(d[1]), "+f"(d[2]), "+f"(d[3])
        : "r"(a[0]), "r"(a[1]), "r"(a[2]), "r"(a[3]), "r"(b[0]), "r"(b[1]));
}

// Row stride in 32-bit words: 16 data + 24 pad = 40; LDS.64 frags conflict-free.
#define RS 40

__device__ __forceinline__
void gemm_bf16x3_body(const uint32_t* __restrict__ Ahl_g,
                      const uint32_t* __restrict__ Whl_g,
                      const float* __restrict__ bias,
                      float* __restrict__ C,
                      int M, int N, int K)
{
    __shared__ uint32_t Ahl[128 * RS];   // 20 KB
    __shared__ uint32_t Bhl[64 * RS];    // 10 KB

    const int tid  = threadIdx.x;
    const int warp = tid >> 5;
    const int lane = tid & 31;
    const int wm   = warp >> 1;        // 0..3 -> m offset wm*32
    const int wn   = warp & 1;         // 0..1 -> n offset wn*32
    const int lr   = lane >> 2;        // 0..7
    const int lc   = lane & 3;         // 0..3
    const int r0   = blockIdx.y * 128;
    const int c0   = blockIdx.x * 64;

    // global load indices (word units == element units)
    const int ar = tid >> 1;           // A row 0..127
    const int ac = (tid & 1) * 8;      // A word col 0 or 8
    const int br = tid >> 2;           // B row 0..63
    const int bc = (tid & 3) * 4;      // B word col 0,4,8,12

    const uint32_t* Ag = &Ahl_g[(size_t)(r0 + ar) * K + ac];
    const uint32_t* Wg = &Whl_g[(size_t)(c0 + br) * K + bc];

    float acc[2][4][4];
#pragma unroll
    for (int mt = 0; mt < 2; mt++)
#pragma unroll
        for (int nt = 0; nt < 4; nt++)
#pragma unroll
            for (int r = 0; r < 4; r++) acc[mt][nt][r] = 0.f;

    // prologue prefetch (tile 0)
    uint4 apv0 = *reinterpret_cast<const uint4*>(Ag);
    uint4 apv1 = *reinterpret_cast<const uint4*>(Ag + 4);
    uint4 bpv  = *reinterpret_cast<const uint4*>(Wg);

    for (int k0 = 0; k0 < K; k0 += 16) {
        // store prefetched tile to smem (pure STS.128)
        *reinterpret_cast<uint4*>(&Ahl[ar * RS + ac])     = apv0;
        *reinterpret_cast<uint4*>(&Ahl[ar * RS + ac + 4]) = apv1;
        *reinterpret_cast<uint4*>(&Bhl[br * RS + bc])     = bpv;
        __syncthreads();

        // prefetch next tile while MMAs below execute
        if (k0 + 16 < K) {
            apv0 = *reinterpret_cast<const uint4*>(Ag + k0 + 16);
            apv1 = *reinterpret_cast<const uint4*>(Ag + k0 + 20);
            bpv  = *reinterpret_cast<const uint4*>(Wg + k0 + 16);
        }

        // fragment loads: 16 LDS.64 per warp, conflict-free
        uint32_t ah[2][4], al[2][4], bh[4][2], bl[4][2];
#pragma unroll
        for (int mt = 0; mt < 2; mt++) {
            const int rbase = (wm * 32 + mt * 16 + lr) * RS;
            const uint2 p00 = *reinterpret_cast<const uint2*>(&Ahl[rbase + lc * 2]);
            const uint2 p10 = *reinterpret_cast<const uint2*>(&Ahl[rbase + 8 * RS + lc * 2]);
            const uint2 p01 = *reinterpret_cast<const uint2*>(&Ahl[rbase + (lc + 4) * 2]);
            const uint2 p11 = *reinterpret_cast<const uint2*>(&Ahl[rbase + 8 * RS + (lc + 4) * 2]);
            ah[mt][0] = p00.x; al[mt][0] = p00.y;
            ah[mt][1] = p10.x; al[mt][1] = p10.y;
            ah[mt][2] = p01.x; al[mt][2] = p01.y;
            ah[mt][3] = p11.x; al[mt][3] = p11.y;
        }
#pragma unroll
        for (int nt = 0; nt < 4; nt++) {
            const int rbase = (wn * 32 + nt * 8 + lr) * RS;
            const uint2 q0 = *reinterpret_cast<const uint2*>(&Bhl[rbase + lc * 2]);
            const uint2 q1 = *reinterpret_cast<const uint2*>(&Bhl[rbase + (lc + 4) * 2]);
            bh[nt][0] = q0.x; bl[nt][0] = q0.y;
            bh[nt][1] = q1.x; bl[nt][1] = q1.y;
        }

#pragma unroll
        for (int mt = 0; mt < 2; mt++)
#pragma unroll
            for (int nt = 0; nt < 4; nt++) {
                mma_bf16(acc[mt][nt], ah[mt], bl[nt]);   // hi*lo
                mma_bf16(acc[mt][nt], al[mt], bh[nt]);   // lo*hi
                mma_bf16(acc[mt][nt], ah[mt], bh[nt]);   // hi*hi
            }
        __syncthreads();
    }

    // epilogue
#pragma unroll
    for (int mt = 0; mt < 2; mt++) {
        const int row = r0 + wm * 32 + mt * 16 + lr;
#pragma unroll
        for (int nt = 0; nt < 4; nt++) {
            const int col = c0 + wn * 32 + nt * 8 + lc * 2;
            const float b0v = bias[col], b1v = bias[col + 1];
            float2 s0, s1;
            s0.x = acc[mt][nt][0] + b0v; s0.y = acc[mt][nt][1] + b1v;
            s1.x = acc[mt][nt][2] + b0v; s1.y = acc[mt][nt][3] + b1v;
            *reinterpret_cast<float2*>(&C[(size_t)row * N + col])       = s0;
            *reinterpret_cast<float2*>(&C[(size_t)(row + 8) * N + col]) = s1;
        }
    }
}

// Wrappers referencing __device__ globals directly
__global__ __launch_bounds__(256)
void qkv_gemm_kernel(const float* __restrict__ qkv_b)
{
    gemm_bf16x3_body(g_xhl, g_wqkv, qkv_b, g_qkv, M_ROWS, QKV_N, DIM);
}

__global__ __launch_bounds__(256)
void proj_gemm_kernel(const float* __restrict__ proj_b,
                      float* __restrict__ out)
{
    gemm_bf16x3_body(g_ctxhl, g_wproj, proj_b, out, M_ROWS, DIM, DIM);
}

// ---------------------------------------------------------------------------
// Fused attention: one block per (window b, head h).
// Writes ctx directly in interleaved {hi,lo} bf16x2 format for proj GEMM.
// ---------------------------------------------------------------------------
#define QPAD 52

__global__ __launch_bounds__(256)
void attn_kernel(float* __restrict__ attn_out, int write_attn)
{
    const int bh = blockIdx.x;
    const int b  = bh / NHEAD;
    const int h  = bh % NHEAD;
    const int tid = threadIdx.x;
    const int mb = b % NWIN;

    __shared__ float4 qs[QPAD * 9];
    __shared__ float4 ksT4[8 * QPAD];
    __shared__ float4 vs[NTOK * 8];
    __shared__ float  s[NTOK * 56];

    const size_t row0 = (size_t)b * NTOK;
    const int qoff = h * HDIM;
    const float scale = 0.1767766952966369f;

    for (int e = tid; e < QPAD * 8; e += 256) {
        const int i = e >> 3, c = e & 7;
        if (i < NTOK) {
            const size_t base = (row0 + i) * QKV_N + qoff + c * 4;
            float4 qv = *reinterpret_cast<const float4*>(&g_qkv[base]);
            qv.x *= scale; qv.y *= scale; qv.z *= scale; qv.w *= scale;
            qs[i * 9 + c] = qv;
            ksT4[c * QPAD + i] = *reinterpret_cast<const float4*>(&g_qkv[base + DIM]);
            vs[i * 8 + c] = *reinterpret_cast<const float4*>(&g_qkv[base + 2 * DIM]);
        } else {
            const float4 z = make_float4(0.f, 0.f, 0.f, 0.f);
            qs[i * 9 + c] = z;
            ksT4[c * QPAD + i] = z;
        }
    }
    __syncthreads();

    const float* bm = &g_bm[(size_t)(mb * NHEAD + h) * NN];
    if (tid < 169) {
        const int ti = tid / 13, tj = tid % 13;
        const int i0 = ti * 4, j0 = tj * 4;
        float acc[4][4];
#pragma unroll
        for (int u = 0; u < 4; u++)
#pragma unroll
            for (int v = 0; v < 4; v++) acc[u][v] = 0.f;
#pragma unroll
        for (int c = 0; c < 8; c++) {
            float4 qv[4], kv[4];
#pragma unroll
            for (int u = 0; u < 4; u++) qv[u] = qs[(i0 + u) * 9 + c];
#pragma unroll
            for (int v = 0; v < 4; v++) kv[v] = ksT4[c * QPAD + j0 + v];
#pragma unroll
            for (int u = 0; u < 4; u++)
#pragma unroll
                for (int v = 0; v < 4; v++)
                    acc[u][v] += qv[u].x * kv[v].x + qv[u].y * kv[v].y
                               + qv[u].z * kv[v].z + qv[u].w * kv[v].w;
        }
#pragma unroll
        for (int u = 0; u < 4; u++) {
            const int i = i0 + u;
            if (i < NTOK) {
#pragma unroll
                for (int v = 0; v < 4; v++) {
                    const int j = j0 + v;
                    if (j < NTOK)
                        s[i * 56 + j] = acc[u][v] + bm[i * NTOK + j];
                }
            }
        }
    }
    __syncthreads();

    {
        const int row = tid >> 2;
        const int q4  = tid & 3;
        const bool act = (row < NTOK);
        float* rowp = &s[(act ? row : 0) * 56];
        float mx = -1e30f;
        if (act) for (int j = q4; j < NTOK; j += 4) mx = fmaxf(mx, rowp[j]);
        mx = fmaxf(mx, __shfl_xor_sync(0xffffffffu, mx, 1));
        mx = fmaxf(mx, __shfl_xor_sync(0xffffffffu, mx, 2));
        float sum = 0.f;
        if (act) {
            for (int j = q4; j < NTOK; j += 4) {
                const float ev = __expf(rowp[j] - mx);
                rowp[j] = ev;
                sum += ev;
            }
        }
        sum += __shfl_xor_sync(0xffffffffu, sum, 1);
        sum += __shfl_xor_sync(0xffffffffu, sum, 2);
        if (act) {
            const float inv = 1.f / sum;
            for (int j = q4; j < NTOK; j += 4) rowp[j] *= inv;
        }
    }
    __syncthreads();

    if (write_attn) {
        float* ao = &attn_out[(size_t)bh * NN];
        for (int e = tid; e < NN; e += 256) {
            const int i = e / NTOK, j = e - i * NTOK;
            ao[e] = s[i * 56 + j];
        }
    }

    if (tid < 200) {
        const int ip = tid >> 3, d4 = tid & 7;
        const int i0 = ip * 2;
        float4 a0 = make_float4(0.f, 0.f, 0.f, 0.f);
        float4 a1 = make_float4(0.f, 0.f, 0.f, 0.f);
        const float* s0 = &s[i0 * 56];
        const bool two = (i0 + 1 < NTOK);
#pragma unroll
        for (int j = 0; j < NTOK; j++) {
            const float4 vv = vs[j * 8 + d4];
            const float p0 = s0[j];
            a0.x += p0 * vv.x; a0.y += p0 * vv.y;
            a0.z += p0 * vv.z; a0.w += p0 * vv.w;
            const float p1 = two ? s0[56 + j] : 0.f;
            a1.x += p1 * vv.x; a1.y += p1 * vv.y;
            a1.z += p1 * vv.z; a1.w += p1 * vv.w;
        }
        // store ctx as interleaved {hi,lo} words for proj GEMM
        const uint2 p0a = split_pair(make_float2(a0.x, a0.y));
        const uint2 p0b = split_pair(make_float2(a0.z, a0.w));
        *reinterpret_cast<uint4*>(&g_ctxhl[(row0 + i0) * DIM + qoff + d4 * 4]) =
            make_uint4(p0a.x, p0a.y, p0b.x, p0b.y);
        if (two) {
            const uint2 p1a = split_pair(make_float2(a1.x, a1.y));
            const uint2 p1b = split_pair(make_float2(a1.z, a1.w));
            *reinterpret_cast<uint4*>(&g_ctxhl[(row0 + i0 + 1) * DIM + qoff + d4 * 4]) =
                make_uint4(p1a.x, p1a.y, p1b.x, p1b.y);
        }
    }
}

extern "C" void kernel_launch(void* const* d_in, const int* in_sizes, int n_in,
                              void* d_out, int out_size)
{
    const float* x      = (const float*)d_in[0];
    const float* mask   = (const float*)d_in[1];
    const float* qkv_w  = (const float*)d_in[2];
    const float* qkv_b  = (const float*)d_in[3];
    const float* proj_w = (const float*)d_in[4];
    const float* proj_b = (const float*)d_in[5];
    const float* rpb    = (const float*)d_in[6];
    const int*   relidx = (const int*)d_in[7];
    float* out = (float*)d_out;

    const long out_elems  = (long)M_ROWS * DIM;                 // 38,535,168
    const long attn_elems = (long)B_TOT * NHEAD * NN;           // 59,006,976
    const int write_attn = ((long)out_size >= out_elems + attn_elems) ? 1 : 0;
    float* attn_out = out + out_elems;

    // 0) conversions + bias/mask table
    cvt_x_kernel<<<(M_ROWS * DIM / 2 + 255) / 256, 256>>>(x);
    cvt_w_kernel<<<(QKV_N * DIM / 2 + 255) / 256, 256>>>(qkv_w, proj_w);
    bm_kernel<<<NWIN * NHEAD, 256>>>(mask, rpb, relidx);

    // 1) QKV GEMM: [200704,192] @ [192,576] (bf16x3, pre-split inputs)
    qkv_gemm_kernel<<<dim3(QKV_N / 64, M_ROWS / 128), 256>>>(qkv_b);

    // 2) fused window attention (writes ctx in hi/lo format)
    attn_kernel<<<B_TOT * NHEAD, 256>>>(attn_out, write_attn);

    // 3) projection: [200704,192] @ [192,192] (bf16x3, pre-split inputs)
    proj_gemm_kernel<<<dim3(DIM / 64, M_ROWS / 128), 256>>>(proj_b, out);
}

// round 16
// speedup vs baseline: 1.0312x; 1.0312x over previous
#include <cuda_runtime.h>
#include <cuda_bf16.h>
#include <math.h>
#include <stdint.h>

#define B_TOT   4096
#define NWIN    64
#define NTOK    49
#define DIM     192
#define NHEAD   6
#define HDIM    32
#define M_ROWS  (B_TOT * NTOK)     /* 200704 */
#define QKV_N   576
#define NN      (NTOK * NTOK)      /* 2401 */

// Scratch (no cudaMalloc allowed); referenced directly from kernels.
__device__ float    g_qkv[(size_t)M_ROWS * QKV_N];        // 462 MB fp32
__device__ uint32_t g_ctxhl[(size_t)M_ROWS * DIM];        // 154 MB {hi,lo} words
__device__ float    g_bm[(size_t)NWIN * NHEAD * NN];      // 3.7 MB bias+mask

__device__ __forceinline__ uint32_t pack_bf16x2(float x, float y) {
    __nv_bfloat162 t = __floats2bfloat162_rn(x, y);   // x -> low 16 bits
    return *reinterpret_cast<uint32_t*>(&t);
}

// ---------------------------------------------------------------------------
// Precompute bm[(mb*NHEAD+h)][e] = rpb[rel_idx[e]*NHEAD+h] + mask[mb][e]
// ---------------------------------------------------------------------------
__global__ __launch_bounds__(256)
void bm_kernel(const float* __restrict__ mask,
               const float* __restrict__ rpb_table,
               const int*   __restrict__ rel_idx)
{
    const int mb = blockIdx.x / NHEAD;
    const int h  = blockIdx.x % NHEAD;
    float* dst = &g_bm[(size_t)blockIdx.x * NN];
    const float* msk = &mask[(size_t)mb * NN];
    for (int e = threadIdx.x; e < NN; e += 256)
        dst[e] = rpb_table[rel_idx[e] * NHEAD + h] + msk[e];
}

// ---------------------------------------------------------------------------
// bf16x3 tensor-core GEMM with INTERLEAVED hi/lo smem ({hi,lo} uint2 pairs):
// every fragment load is one LDS.64, every split store one STS.64.
// C[M,N] = A[M,K] @ W^T + bias, W row-major [N,K].
// BM=128, BN=64, BK=16, 256 threads (8 warps, 4x2 grid of 32x32 warp tiles).
// (R13-proven; tcgen05 is unavailable: harness targets sm_103 without 'a'.)
// ---------------------------------------------------------------------------
__device__ __forceinline__ void mma_bf16(float* d, const uint32_t* a, const uint32_t* b) {
    asm volatile(
        "mma.sync.aligned.m16n8k16.row.col.f32.bf16.bf16.f32 "
        "{%0,%1,%2,%3}, {%4,%5,%6,%7}, {%8,%9}, {%0,%1,%2,%3};"
        : "+f"(d[0]), "+f"(d[1]), "+f"(d[2]), "+f"(d[3])
        : "r"(a[0]), "r"(a[1]), "r"(a[2]), "r"(a[3]), "r"(b[0]), "r"(b[1]));
}

#define RS 40

__device__ __forceinline__
void gemm_bf16x3_body(const float* __restrict__ A,
                      const float* __restrict__ W,
                      const float* __restrict__ bias,
                      float* __restrict__ C,
                      int M, int N, int K)
{
    __shared__ uint32_t Ahl[128 * RS];   // 20 KB
    __shared__ uint32_t Bhl[64 * RS];    // 10 KB

    const int tid  = threadIdx.x;
    const int warp = tid >> 5;
    const int lane = tid & 31;
    const int wm   = warp >> 1;
    const int wn   = warp & 1;
    const int lr   = lane >> 2;
    const int lc   = lane & 3;
    const int r0   = blockIdx.y * 128;
    const int c0   = blockIdx.x * 64;

    const int ar = tid >> 1;
    const int ac = (tid & 1) * 8;
    const int br = tid >> 2;
    const int bc = (tid & 3) * 4;

    const float* Ag = &A[(size_t)(r0 + ar) * K + ac];
    const float* Wg = &W[(size_t)(c0 + br) * K + bc];

    float acc[2][4][4];
#pragma unroll
    for (int mt = 0; mt < 2; mt++)
#pragma unroll
        for (int nt = 0; nt < 4; nt++)
#pragma unroll
            for (int r = 0; r < 4; r++) acc[mt][nt][r] = 0.f;

    float ap[8], bp[4];
    {
        const float4 a0 = *reinterpret_cast<const float4*>(Ag);
        const float4 a1 = *reinterpret_cast<const float4*>(Ag + 4);
        ap[0]=a0.x; ap[1]=a0.y; ap[2]=a0.z; ap[3]=a0.w;
        ap[4]=a1.x; ap[5]=a1.y; ap[6]=a1.z; ap[7]=a1.w;
        const float4 b0 = *reinterpret_cast<const float4*>(Wg);
        bp[0]=b0.x; bp[1]=b0.y; bp[2]=b0.z; bp[3]=b0.w;
    }

    for (int k0 = 0; k0 < K; k0 += 16) {
#pragma unroll
        for (int i = 0; i < 4; i++) {
            const float f0 = ap[2 * i], f1 = ap[2 * i + 1];
            const float h0 = __bfloat162float(__float2bfloat16_rn(f0));
            const float h1 = __bfloat162float(__float2bfloat16_rn(f1));
            const int col = ac / 2 + i;
            *reinterpret_cast<uint2*>(&Ahl[ar * RS + col * 2]) =
                make_uint2(pack_bf16x2(h0, h1), pack_bf16x2(f0 - h0, f1 - h1));
        }
#pragma unroll
        for (int i = 0; i < 2; i++) {
            const float f0 = bp[2 * i], f1 = bp[2 * i + 1];
            const float h0 = __bfloat162float(__float2bfloat16_rn(f0));
            const float h1 = __bfloat162float(__float2bfloat16_rn(f1));
            const int col = bc / 2 + i;
            *reinterpret_cast<uint2*>(&Bhl[br * RS + col * 2]) =
                make_uint2(pack_bf16x2(h0, h1), pack_bf16x2(f0 - h0, f1 - h1));
        }
        __syncthreads();

        if (k0 + 16 < K) {
            const float4 a0 = *reinterpret_cast<const float4*>(Ag + k0 + 16);
            const float4 a1 = *reinterpret_cast<const float4*>(Ag + k0 + 20);
            ap[0]=a0.x; ap[1]=a0.y; ap[2]=a0.z; ap[3]=a0.w;
            ap[4]=a1.x; ap[5]=a1.y; ap[6]=a1.z; ap[7]=a1.w;
            const float4 b0 = *reinterpret_cast<const float4*>(Wg + k0 + 16);
            bp[0]=b0.x; bp[1]=b0.y; bp[2]=b0.z; bp[3]=b0.w;
        }

        uint32_t ah[2][4], al[2][4], bh[4][2], bl[4][2];
#pragma unroll
        for (int mt = 0; mt < 2; mt++) {
            const int rbase = (wm * 32 + mt * 16 + lr) * RS;
            const uint2 p00 = *reinterpret_cast<const uint2*>(&Ahl[rbase + lc * 2]);
            const uint2 p10 = *reinterpret_cast<const uint2*>(&Ahl[rbase + 8 * RS + lc * 2]);
            const uint2 p01 = *reinterpret_cast<const uint2*>(&Ahl[rbase + (lc + 4) * 2]);
            const uint2 p11 = *reinterpret_cast<const uint2*>(&Ahl[rbase + 8 * RS + (lc + 4) * 2]);
            ah[mt][0] = p00.x; al[mt][0] = p00.y;
            ah[mt][1] = p10.x; al[mt][1] = p10.y;
            ah[mt][2] = p01.x; al[mt][2] = p01.y;
            ah[mt][3] = p11.x; al[mt][3] = p11.y;
        }
#pragma unroll
        for (int nt = 0; nt < 4; nt++) {
            const int rbase = (wn * 32 + nt * 8 + lr) * RS;
            const uint2 q0 = *reinterpret_cast<const uint2*>(&Bhl[rbase + lc * 2]);
            const uint2 q1 = *reinterpret_cast<const uint2*>(&Bhl[rbase + (lc + 4) * 2]);
            bh[nt][0] = q0.x; bl[nt][0] = q0.y;
            bh[nt][1] = q1.x; bl[nt][1] = q1.y;
        }

#pragma unroll
        for (int mt = 0; mt < 2; mt++)
#pragma unroll
            for (int nt = 0; nt < 4; nt++) {
                mma_bf16(acc[mt][nt], ah[mt], bl[nt]);   // hi*lo
                mma_bf16(acc[mt][nt], al[mt], bh[nt]);   // lo*hi
                mma_bf16(acc[mt][nt], ah[mt], bh[nt]);   // hi*hi
            }
        __syncthreads();
    }

#pragma unroll
    for (int mt = 0; mt < 2; mt++) {
        const int row = r0 + wm * 32 + mt * 16 + lr;
#pragma unroll
        for (int nt = 0; nt < 4; nt++) {
            const int col = c0 + wn * 32 + nt * 8 + lc * 2;
            const float b0v = bias[col], b1v = bias[col + 1];
            float2 s0, s1;
            s0.x = acc[mt][nt][0] + b0v; s0.y = acc[mt][nt][1] + b1v;
            s1.x = acc[mt][nt][2] + b0v; s1.y = acc[mt][nt][3] + b1v;
            *reinterpret_cast<float2*>(&C[(size_t)row * N + col])       = s0;
            *reinterpret_cast<float2*>(&C[(size_t)(row + 8) * N + col]) = s1;
        }
    }
}

__global__ __launch_bounds__(256)
void qkv_gemm_kernel(const float* __restrict__ x,
                     const float* __restrict__ qkv_w,
                     const float* __restrict__ qkv_b)
{
    gemm_bf16x3_body(x, qkv_w, qkv_b, g_qkv, M_ROWS, QKV_N, DIM);
}

// proj consumes interleaved {hi,lo} ctx written by attn (values already split):
// treat hi word as "value" by unpacking? No: reuse same body with fp32 read is
// wrong. Instead a dedicated body variant reading pre-split A words directly.
__device__ __forceinline__
void gemm_bf16x3_presplitA_body(const uint32_t* __restrict__ Ahl_g,
                                const float* __restrict__ W,
                                const float* __restrict__ bias,
                                float* __restrict__ C,
                                int M, int N, int K)
{
    __shared__ uint32_t Ahl[128 * RS];
    __shared__ uint32_t Bhl[64 * RS];

    const int tid  = threadIdx.x;
    const int warp = tid >> 5;
    const int lane = tid & 31;
    const int wm   = warp >> 1;
    const int wn   = warp & 1;
    const int lr   = lane >> 2;
    const int lc   = lane & 3;
    const int r0   = blockIdx.y * 128;
    const int c0   = blockIdx.x * 64;

    const int ar = tid >> 1;
    const int ac = (tid & 1) * 8;      // element cols (words: interleaved 2/elt-pair)
    const int br = tid >> 2;
    const int bc = (tid & 3) * 4;

    // A stored as {hi,lo} words per element pair: row has K words (K elements -> K words? )
    // g_ctxhl layout: word index = row*K + elem, each word {hi,lo} packed? No:
    // attn writes PAIRS: per 2 elements -> 2 words {hiPair, loPair}. Word col c
    // covers elements 2c,2c+1 at words [2c]=hi, [2c+1]=lo. ac elements -> word ac.
    const uint32_t* Ag = &Ahl_g[(size_t)(r0 + ar) * K + ac];
    const float*    Wg = &W[(size_t)(c0 + br) * K + bc];

    float acc[2][4][4];
#pragma unroll
    for (int mt = 0; mt < 2; mt++)
#pragma unroll
        for (int nt = 0; nt < 4; nt++)
#pragma unroll
            for (int r = 0; r < 4; r++) acc[mt][nt][r] = 0.f;

    uint4 apv0 = *reinterpret_cast<const uint4*>(Ag);
    uint4 apv1 = *reinterpret_cast<const uint4*>(Ag + 4);
    float bp[4];
    {
        const float4 b0 = *reinterpret_cast<const float4*>(Wg);
        bp[0]=b0.x; bp[1]=b0.y; bp[2]=b0.z; bp[3]=b0.w;
    }

    for (int k0 = 0; k0 < K; k0 += 16) {
        *reinterpret_cast<uint4*>(&Ahl[ar * RS + ac])     = apv0;
        *reinterpret_cast<uint4*>(&Ahl[ar * RS + ac + 4]) = apv1;
#pragma unroll
        for (int i = 0; i < 2; i++) {
            const float f0 = bp[2 * i], f1 = bp[2 * i + 1];
            const float h0 = __bfloat162float(__float2bfloat16_rn(f0));
            const float h1 = __bfloat162float(__float2bfloat16_rn(f1));
            const int col = bc / 2 + i;
            *reinterpret_cast<uint2*>(&Bhl[br * RS + col * 2]) =
                make_uint2(pack_bf16x2(h0, h1), pack_bf16x2(f0 - h0, f1 - h1));
        }
        __syncthreads();

        if (k0 + 16 < K) {
            apv0 = *reinterpret_cast<const uint4*>(Ag + k0 + 16);
            apv1 = *reinterpret_cast<const uint4*>(Ag + k0 + 20);
            const float4 b0 = *reinterpret_cast<const float4*>(Wg + k0 + 16);
            bp[0]=b0.x; bp[1]=b0.y; bp[2]=b0.z; bp[3]=b0.w;
        }

        uint32_t ah[2][4], al[2][4], bh[4][2], bl[4][2];
#pragma unroll
        for (int mt = 0; mt < 2; mt++) {
            const int rbase = (wm * 32 + mt * 16 + lr) * RS;
            const uint2 p00 = *reinterpret_cast<const uint2*>(&Ahl[rbase + lc * 2]);
            const uint2 p10 = *reinterpret_cast<const uint2*>(&Ahl[rbase + 8 * RS + lc * 2]);
            const uint2 p01 = *reinterpret_cast<const uint2*>(&Ahl[rbase + (lc + 4) * 2]);
            const uint2 p11 = *reinterpret_cast<const uint2*>(&Ahl[rbase + 8 * RS + (lc + 4) * 2]);
            ah[mt][0] = p00.x; al[mt][0] = p00.y;
            ah[mt][1] = p10.x; al[mt][1] = p10.y;
            ah[mt][2] = p01.x; al[mt][2] = p01.y;
            ah[mt][3] = p11.x; al[mt][3] = p11.y;
        }
#pragma unroll
        for (int nt = 0; nt < 4; nt++) {
            const int rbase = (wn * 32 + nt * 8 + lr) * RS;
            const uint2 q0 = *reinterpret_cast<const uint2*>(&Bhl[rbase + lc * 2]);
            const uint2 q1 = *reinterpret_cast<const uint2*>(&Bhl[rbase + (lc + 4) * 2]);
            bh[nt][0] = q0.x; bl[nt][0] = q0.y;
            bh[nt][1] = q1.x; bl[nt][1] = q1.y;
        }

#pragma unroll
        for (int mt = 0; mt < 2; mt++)
#pragma unroll
            for (int nt = 0; nt < 4; nt++) {
                mma_bf16(acc[mt][nt], ah[mt], bl[nt]);
                mma_bf16(acc[mt][nt], al[mt], bh[nt]);
                mma_bf16(acc[mt][nt], ah[mt], bh[nt]);
            }
        __syncthreads();
    }

#pragma unroll
    for (int mt = 0; mt < 2; mt++) {
        const int row = r0 + wm * 32 + mt * 16 + lr;
#pragma unroll
        for (int nt = 0; nt < 4; nt++) {
            const int col = c0 + wn * 32 + nt * 8 + lc * 2;
            const float b0v = bias[col], b1v = bias[col + 1];
            float2 s0, s1;
            s0.x = acc[mt][nt][0] + b0v; s0.y = acc[mt][nt][1] + b1v;
            s1.x = acc[mt][nt][2] + b0v; s1.y = acc[mt][nt][3] + b1v;
            *reinterpret_cast<float2*>(&C[(size_t)row * N + col])       = s0;
            *reinterpret_cast<float2*>(&C[(size_t)(row + 8) * N + col]) = s1;
        }
    }
}

__global__ __launch_bounds__(256)
void proj_gemm_kernel(const float* __restrict__ proj_w,
                      const float* __restrict__ proj_b,
                      float* __restrict__ out)
{
    gemm_bf16x3_presplitA_body(g_ctxhl, proj_w, proj_b, out, M_ROWS, DIM, DIM);
}

// ---------------------------------------------------------------------------
// Fused attention with hybrid MUFU/FMA exp softmax.
// Writes ctx as interleaved {hiPair, loPair} words (per 2 elements).
// ---------------------------------------------------------------------------
#define QPAD 52

__device__ __forceinline__ uint2 split_pair(float2 f) {
    const float h0 = __bfloat162float(__float2bfloat16_rn(f.x));
    const float h1 = __bfloat162float(__float2bfloat16_rn(f.y));
    return make_uint2(pack_bf16x2(h0, h1), pack_bf16x2(f.x - h0, f.y - h1));
}

// FMA-pipe exp: 2^(x*log2e) via magic-number round + degree-5 poly + bit splice.
__device__ __forceinline__ float exp_fma(float x) {
    float t = fmaxf(x * 1.4426950408889634f, -125.0f);
    const float magic = 12582912.0f;             // 2^23 + 2^22
    const float tm = t + magic;
    const int   ni = __float_as_int(tm) - 0x4B400000;
    const float fn = tm - magic;
    const float f  = t - fn;                     // f in [-0.5, 0.5]
    float p = fmaf(f, 0.0013333558f, 0.0096181291f);
    p = fmaf(f, p, 0.055504109f);
    p = fmaf(f, p, 0.24022651f);
    p = fmaf(f, p, 0.69314718f);
    p = fmaf(f, p, 1.0f);
    return __int_as_float((ni + 127) << 23) * p;
}

__global__ __launch_bounds__(256)
void attn_kernel(float* __restrict__ attn_out, int write_attn)
{
    const int bh = blockIdx.x;
    const int b  = bh / NHEAD;
    const int h  = bh % NHEAD;
    const int tid = threadIdx.x;
    const int mb = b % NWIN;

    __shared__ float4 qs[QPAD * 9];
    __shared__ float4 ksT4[8 * QPAD];
    __shared__ float4 vs[NTOK * 8];
    __shared__ float  s[NTOK * 56];

    const size_t row0 = (size_t)b * NTOK;
    const int qoff = h * HDIM;
    const float scale = 0.1767766952966369f;

    for (int e = tid; e < QPAD * 8; e += 256) {
        const int i = e >> 3, c = e & 7;
        if (i < NTOK) {
            const size_t base = (row0 + i) * QKV_N + qoff + c * 4;
            float4 qv = *reinterpret_cast<const float4*>(&g_qkv[base]);
            qv.x *= scale; qv.y *= scale; qv.z *= scale; qv.w *= scale;
            qs[i * 9 + c] = qv;
            ksT4[c * QPAD + i] = *reinterpret_cast<const float4*>(&g_qkv[base + DIM]);
            vs[i * 8 + c] = *reinterpret_cast<const float4*>(&g_qkv[base + 2 * DIM]);
        } else {
            const float4 z = make_float4(0.f, 0.f, 0.f, 0.f);
            qs[i * 9 + c] = z;
            ksT4[c * QPAD + i] = z;
        }
    }
    __syncthreads();

    const float* bm = &g_bm[(size_t)(mb * NHEAD + h) * NN];
    if (tid < 169) {
        const int ti = tid / 13, tj = tid % 13;
        const int i0 = ti * 4, j0 = tj * 4;
        float acc[4][4];
#pragma unroll
        for (int u = 0; u < 4; u++)
#pragma unroll
            for (int v = 0; v < 4; v++) acc[u][v] = 0.f;
#pragma unroll
        for (int c = 0; c < 8; c++) {
            float4 qv[4], kv[4];
#pragma unroll
            for (int u = 0; u < 4; u++) qv[u] = qs[(i0 + u) * 9 + c];
#pragma unroll
            for (int v = 0; v < 4; v++) kv[v] = ksT4[c * QPAD + j0 + v];
#pragma unroll
            for (int u = 0; u < 4; u++)
#pragma unroll
                for (int v = 0; v < 4; v++)
                    acc[u][v] += qv[u].x * kv[v].x + qv[u].y * kv[v].y
                               + qv[u].z * kv[v].z + qv[u].w * kv[v].w;
        }
#pragma unroll
        for (int u = 0; u < 4; u++) {
            const int i = i0 + u;
            if (i < NTOK) {
#pragma unroll
                for (int v = 0; v < 4; v++) {
                    const int j = j0 + v;
                    if (j < NTOK)
                        s[i * 56 + j] = acc[u][v] + bm[i * NTOK + j];
                }
            }
        }
    }
    __syncthreads();

    // softmax: quad per row; hybrid exp (1/3 FMA-pipe, 2/3 MUFU) balances pipes.
    {
        const int row = tid >> 2;
        const int q4  = tid & 3;
        const bool act = (row < NTOK);
        float* rowp = &s[(act ? row : 0) * 56];
        float mx = -1e30f;
        if (act) for (int j = q4; j < NTOK; j += 4) mx = fmaxf(mx, rowp[j]);
        mx = fmaxf(mx, __shfl_xor_sync(0xffffffffu, mx, 1));
        mx = fmaxf(mx, __shfl_xor_sync(0xffffffffu, mx, 2));
        float sum = 0.f;
        if (act) {
            int idx = 0;
            for (int j = q4; j < NTOK; j += 4, idx++) {
                const float xv = rowp[j] - mx;
                const float ev = (idx % 3 == 0) ? exp_fma(xv) : __expf(xv);
                rowp[j] = ev;
                sum += ev;
            }
        }
        sum += __shfl_xor_sync(0xffffffffu, sum, 1);
        sum += __shfl_xor_sync(0xffffffffu, sum, 2);
        if (act) {
            const float inv = 1.f / sum;
            for (int j = q4; j < NTOK; j += 4) rowp[j] *= inv;
        }
    }
    __syncthreads();

    if (write_attn) {
        float* ao = &attn_out[(size_t)bh * NN];
        for (int e = tid; e < NN; e += 256) {
            const int i = e / NTOK, j = e - i * NTOK;
            ao[e] = s[i * 56 + j];
        }
    }

    if (tid < 200) {
        const int ip = tid >> 3, d4 = tid & 7;
        const int i0 = ip * 2;
        float4 a0 = make_float4(0.f, 0.f, 0.f, 0.f);
        float4 a1 = make_float4(0.f, 0.f, 0.f, 0.f);
        const float* s0 = &s[i0 * 56];
        const bool two = (i0 + 1 < NTOK);
#pragma unroll
        for (int j = 0; j < NTOK; j++) {
            const float4 vv = vs[j * 8 + d4];
            const float p0 = s0[j];
            a0.x += p0 * vv.x; a0.y += p0 * vv.y;
            a0.z += p0 * vv.z; a0.w += p0 * vv.w;
            const float p1 = two ? s0[56 + j] : 0.f;
            a1.x += p1 * vv.x; a1.y += p1 * vv.y;
            a1.z += p1 * vv.z; a1.w += p1 * vv.w;
        }
        const uint2 p0a = split_pair(make_float2(a0.x, a0.y));
        const uint2 p0b = split_pair(make_float2(a0.z, a0.w));
        *reinterpret_cast<uint4*>(&g_ctxhl[(row0 + i0) * DIM + qoff + d4 * 4]) =
            make_uint4(p0a.x, p0a.y, p0b.x, p0b.y);
        if (two) {
            const uint2 p1a = split_pair(make_float2(a1.x, a1.y));
            const uint2 p1b = split_pair(make_float2(a1.z, a1.w));
            *reinterpret_cast<uint4*>(&g_ctxhl[(row0 + i0 + 1) * DIM + qoff + d4 * 4]) =
                make_uint4(p1a.x, p1a.y, p1b.x, p1b.y);
        }
    }
}

extern "C" void kernel_launch(void* const* d_in, const int* in_sizes, int n_in,
                              void* d_out, int out_size)
{
    const float* x      = (const float*)d_in[0];
    const float* mask   = (const float*)d_in[1];
    const float* qkv_w  = (const float*)d_in[2];
    const float* qkv_b  = (const float*)d_in[3];
    const float* proj_w = (const float*)d_in[4];
    const float* proj_b = (const float*)d_in[5];
    const float* rpb    = (const float*)d_in[6];
    const int*   relidx = (const int*)d_in[7];
    float* out = (float*)d_out;

    const long out_elems  = (long)M_ROWS * DIM;                 // 38,535,168
    const long attn_elems = (long)B_TOT * NHEAD * NN;           // 59,006,976
    const int write_attn = ((long)out_size >= out_elems + attn_elems) ? 1 : 0;
    float* attn_out = out + out_elems;

    // 0) bias+mask table
    bm_kernel<<<NWIN * NHEAD, 256>>>(mask, rpb, relidx);

    // 1) QKV GEMM: [200704,192] @ [192,576] (bf16x3, interleaved hi/lo)
    qkv_gemm_kernel<<<dim3(QKV_N / 64, M_ROWS / 128), 256>>>(x, qkv_w, qkv_b);

    // 2) fused window attention (hybrid exp; writes ctx {hi,lo})
    attn_kernel<<<B_TOT * NHEAD, 256>>>(attn_out, write_attn);

    // 3) projection: [200704,192] @ [192,192] (bf16x3, pre-split A)
    proj_gemm_kernel<<<dim3(DIM / 64, M_ROWS / 128), 256>>>(proj_w, proj_b, out);
}